// round 3
// baseline (speedup 1.0000x reference)
#include <cuda_runtime.h>
#include <cstdint>

// GrokkingSNN: B=32768, hidden=512, p=97, 15 steps.
//   cur1[b,j] = P1[x0,j] + P2[x1,j] + b1[j], P = E @ W1half.T  (97x512 each)
//   Only 9409 distinct (x0,x1) pairs -> simulate per pair.
//   mem2 = (sum_t beta2^{15-t} spk_t) @ W2.T + b2 * G
//   Scatter per-pair rows to 32768 output rows.
// R2: occupancy-fixed precompute, coalesced float4 phase-1 loads,
//     packed f32x2 FFMA2 GEMM (bit-identical rounding everywhere).

#define HIDDEN 512
#define PDIM 97
#define NPAIR (PDIM * PDIM)   // 9409
#define NSTEPS 15
#define UPITCH 104

#define SPITCH 68   // Ssm pitch (floats)
#define WP2 65      // packed W2 chunk pitch (in 8-byte words)
#define KC 64       // K-chunk for W2 staging

__device__ float g_P[2 * PDIM * HIDDEN];    // [s][v][j]
__device__ float g_U[NPAIR * UPITCH];       // per-pair output rows (+bias)

__device__ __forceinline__ void ffma2(unsigned long long& d,
                                      unsigned long long a,
                                      unsigned long long b) {
    // two independent IEEE fp32 FMAs (SASS FFMA2) — bit-identical to 2x fmaf
    asm("fma.rn.f32x2 %0, %1, %2, %0;" : "+l"(d) : "l"(a), "l"(b));
}

__device__ __forceinline__ unsigned long long dup_f32(float w) {
    unsigned long long u;
    asm("mov.b64 %0, {%1, %1};" : "=l"(u) : "f"(w));
    return u;
}

__device__ __forceinline__ float2 unpack_f32x2(unsigned long long v) {
    float2 r;
    asm("mov.b64 {%0, %1}, %2;" : "=f"(r.x), "=f"(r.y) : "l"(v));
    return r;
}

// ---------------------------------------------------------------------------
// Kernel A: P[s][v][j] = sum_k E[v][k] * W1[j][s*512+k]
// grid (16 j-tiles of 32, 13 v-tiles of 8, 2 s), 128 threads, 2 v per thread.
// Per-output accumulation: single chain, k ascending (identical to R0).
// ---------------------------------------------------------------------------
__global__ void __launch_bounds__(128) precompute_kernel(
    const float* __restrict__ E, const float* __restrict__ W1)
{
    __shared__ float4 e4[8][HIDDEN / 4];
    const int jt = blockIdx.x, vt = blockIdx.y, s = blockIdx.z;
    const int vbase = vt * 8;
    const int tid = threadIdx.x;

    const float4* E4 = reinterpret_cast<const float4*>(E);
    for (int i = tid; i < 8 * (HIDDEN / 4); i += 128) {
        int vv = i >> 7;
        int k4 = i & 127;
        int v  = vbase + vv;
        float4 z = make_float4(0.f, 0.f, 0.f, 0.f);
        e4[vv][k4] = (v < PDIM) ? __ldg(E4 + v * (HIDDEN / 4) + k4) : z;
    }
    __syncthreads();

    const int j  = jt * 32 + (tid & 31);
    const int r0 = (tid >> 5) * 2;          // v rows r0, r0+1
    const float4* wrow =
        reinterpret_cast<const float4*>(W1 + (size_t)j * (2 * HIDDEN) + s * HIDDEN);

    float acc0 = 0.f, acc1 = 0.f;
#pragma unroll 4
    for (int k4 = 0; k4 < HIDDEN / 4; k4++) {
        float4 w  = __ldg(wrow + k4);
        float4 a0 = e4[r0][k4];
        float4 a1 = e4[r0 + 1][k4];
        acc0 = fmaf(a0.x, w.x, acc0);
        acc0 = fmaf(a0.y, w.y, acc0);
        acc0 = fmaf(a0.z, w.z, acc0);
        acc0 = fmaf(a0.w, w.w, acc0);
        acc1 = fmaf(a1.x, w.x, acc1);
        acc1 = fmaf(a1.y, w.y, acc1);
        acc1 = fmaf(a1.z, w.z, acc1);
        acc1 = fmaf(a1.w, w.w, acc1);
    }

    int vg = vbase + r0;
    if (vg < PDIM)     g_P[(s * PDIM + vg)     * HIDDEN + j] = acc0;
    if (vg + 1 < PDIM) g_P[(s * PDIM + vg + 1) * HIDDEN + j] = acc1;
}

// ---------------------------------------------------------------------------
// Kernel B: per-pair LIF sim -> weighted spike sums S (smem), then
// U = S @ W2.T + b2*G with packed f32x2 FMAs. 148 blocks x 64 pairs, 256 thr.
// ---------------------------------------------------------------------------
__global__ void __launch_bounds__(256, 1) pair_kernel(
    const float* __restrict__ b1, const float* __restrict__ W2,
    const float* __restrict__ b2, const float* __restrict__ pbeta1,
    const float* __restrict__ pbeta2, const float* __restrict__ pthr1)
{
    extern __shared__ float sm[];
    float* Ssm = sm;                                            // [512][SPITCH]
    unsigned long long* W2s =
        reinterpret_cast<unsigned long long*>(sm + 512 * SPITCH); // [112][WP2]

    const float beta1 = fminf(fmaxf(__ldg(pbeta1), 0.1f), 0.9f);
    const float beta2 = fminf(fmaxf(__ldg(pbeta2), 0.1f), 0.9f);
    const float thr1  = fmaxf(__ldg(pthr1), 0.1f);

    const int tid = threadIdx.x;

    // ---------------- phase 1: simulate 64 pairs x 512 h (coalesced) --------
    {
        const int q   = tid >> 2;   // pair slot 0..63
        const int sub = tid & 3;    // h-quarter
        int pp = blockIdx.x * 64 + q;
        if (pp >= NPAIR) pp = 0;    // junk lanes; phase-2 store is guarded
        const int a = pp / PDIM;
        const int b = pp - a * PDIM;
        const float4* p1  = reinterpret_cast<const float4*>(g_P + a * HIDDEN);
        const float4* p2  = reinterpret_cast<const float4*>(g_P + (PDIM + b) * HIDDEN);
        const float4* b14 = reinterpret_cast<const float4*>(b1);

        for (int o = 0; o < 32; o++) {
            const int h4 = sub + 4 * o;            // 0..127
            float4 v1 = __ldg(p1 + h4);
            float4 v2 = __ldg(p2 + h4);
            float4 vb = __ldg(b14 + h4);
            // c = (p1 + p2) + b1  — same order as R0
            float c[4], m[4], S[4];
            bool  sp[4];
            c[0] = __fadd_rn(__fadd_rn(v1.x, v2.x), vb.x);
            c[1] = __fadd_rn(__fadd_rn(v1.y, v2.y), vb.y);
            c[2] = __fadd_rn(__fadd_rn(v1.z, v2.z), vb.z);
            c[3] = __fadd_rn(__fadd_rn(v1.w, v2.w), vb.w);
#pragma unroll
            for (int u = 0; u < 4; u++) { m[u] = 0.f; S[u] = 0.f; sp[u] = false; }
#pragma unroll
            for (int t = 0; t < NSTEPS; t++) {
#pragma unroll
                for (int u = 0; u < 4; u++) {
                    // mem1 = beta1*mem1 + cur1 - reset*thr1 (reference order)
                    float mm = __fadd_rn(__fmul_rn(beta1, m[u]), c[u]);
                    if (sp[u]) mm = __fsub_rn(mm, thr1);
                    sp[u] = (mm > thr1);
                    m[u] = mm;
                    S[u] = fmaf(beta2, S[u], sp[u] ? 1.0f : 0.0f);
                }
            }
            const int h = h4 * 4;
#pragma unroll
            for (int u = 0; u < 4; u++) Ssm[(h + u) * SPITCH + q] = S[u];
        }
    }

    // ---------------- phase 2: U = S @ W2.T (packed f32x2) ------------------
    const int tx = tid & 15;   // 4-pair group
    const int ty = tid >> 4;   // 7-p group

    unsigned long long acc01[7], acc23[7];
#pragma unroll
    for (int i = 0; i < 7; i++) { acc01[i] = 0ull; acc23[i] = 0ull; }

    for (int kb = 0; kb < HIDDEN / KC; kb++) {
        __syncthreads();   // first iter: phase-1 done; later: prev chunk consumed
        for (int idx = tid; idx < PDIM * KC; idx += 256) {
            int p = idx >> 6;
            int k = idx & 63;
            float w = __ldg(W2 + p * HIDDEN + kb * KC + k);
            W2s[p * WP2 + k] = dup_f32(w);
        }
        __syncthreads();

#pragma unroll 4
        for (int k = 0; k < KC; k++) {
            int kg = kb * KC + k;
            ulonglong2 sv = *reinterpret_cast<const ulonglong2*>(
                Ssm + kg * SPITCH + tx * 4);
#pragma unroll
            for (int i = 0; i < 7; i++) {
                unsigned long long w2 = W2s[(ty * 7 + i) * WP2 + k];
                ffma2(acc01[i], sv.x, w2);
                ffma2(acc23[i], sv.y, w2);
            }
        }
    }

    // G = sum_{k=0..14} beta2^k via same recursion as mem2
    float G = 0.0f;
#pragma unroll
    for (int t = 0; t < NSTEPS; t++) G = __fadd_rn(__fmul_rn(beta2, G), 1.0f);

    const int ppb = blockIdx.x * 64 + tx * 4;
#pragma unroll
    for (int i = 0; i < 7; i++) {
        const int p = ty * 7 + i;
        if (p >= PDIM) break;
        const float bg = __ldg(b2 + p) * G;
        float2 f01 = unpack_f32x2(acc01[i]);
        float2 f23 = unpack_f32x2(acc23[i]);
        float av[4] = {f01.x, f01.y, f23.x, f23.y};
#pragma unroll
        for (int jj = 0; jj < 4; jj++) {
            int pp = ppb + jj;
            if (pp < NPAIR) g_U[pp * UPITCH + p] = av[jj] + bg;
        }
    }
}

// ---------------------------------------------------------------------------
// Kernel C: out[b,:] = U[pair(b),:]. One warp per output row.
// ---------------------------------------------------------------------------
__global__ void __launch_bounds__(256) scatter_kernel(
    const int* __restrict__ x, float* __restrict__ out, int B)
{
    int warp = blockIdx.x * 8 + (threadIdx.x >> 5);
    int lane = threadIdx.x & 31;
    if (warp >= B) return;
    int x0 = __ldg(x + 2 * warp);
    int x1 = __ldg(x + 2 * warp + 1);
    const float* u = g_U + (size_t)(x0 * PDIM + x1) * UPITCH;
    float* o = out + (size_t)warp * PDIM;
#pragma unroll
    for (int j = 0; j < 3; j++) o[lane + 32 * j] = u[lane + 32 * j];
    if (lane == 0) o[96] = u[96];
}

// ---------------------------------------------------------------------------
extern "C" void kernel_launch(void* const* d_in, const int* in_sizes, int n_in,
                              void* d_out, int out_size)
{
    const int*   x     = (const int*)  d_in[0];
    const float* E     = (const float*)d_in[1];
    const float* W1    = (const float*)d_in[2];
    const float* b1    = (const float*)d_in[3];
    const float* W2    = (const float*)d_in[4];
    const float* b2    = (const float*)d_in[5];
    const float* beta1 = (const float*)d_in[6];
    const float* beta2 = (const float*)d_in[7];
    const float* thr1  = (const float*)d_in[8];
    // thr2 unused in forward (lif2 reset='none'; output is mem2).

    const int B = in_sizes[0] / 2;

    const int smemB = 512 * SPITCH * (int)sizeof(float)
                    + 112 * WP2 * (int)sizeof(unsigned long long); // 197504 B
    cudaFuncSetAttribute(pair_kernel, cudaFuncAttributeMaxDynamicSharedMemorySize, smemB);

    precompute_kernel<<<dim3(16, 13, 2), 128>>>(E, W1);
    pair_kernel<<<148, 256, smemB>>>(b1, W2, b2, beta1, beta2, thr1);
    scatter_kernel<<<(B + 7) / 8, 256>>>(x, (float*)d_out, B);
}

// round 4
// speedup vs baseline: 1.3354x; 1.3354x over previous
#include <cuda_runtime.h>
#include <cstdint>

// GrokkingSNN: B=32768, hidden=512, p=97, 15 steps.
//   cur1[b,j] = P1[x0,j] + P2[x1,j] + b1[j], P = E @ W1half.T  (97x512 each)
//   9409 distinct (x0,x1) pairs -> simulate per pair.
//   mem2 = (sum_t beta2^{15-t} spk_t) @ W2.T + b2 * G; scatter to 32768 rows.
// R4: smem-tiled coalesced precompute (kills L1tex wavefront storm);
//     phase-1 prefetch + predicate->FSEL/FFMA (bit-identical);
//     phase-2 packed f32x2 GEMM unchanged.

#define HIDDEN 512
#define PDIM 97
#define NPAIR (PDIM * PDIM)   // 9409
#define NSTEPS 15
#define UPITCH 104

#define SPITCH 68   // Ssm pitch (floats)
#define WP2 65      // packed W2 chunk pitch (8-byte words)
#define KC 64       // K-chunk for W2 staging

// precompute tiling
#define PJT 32      // j per block
#define PVT 16      // v per block
#define PKC 128     // k chunk (floats)
#define W1P4 33     // W1 chunk pitch in float4 (32+1: conflict-free LDS.128)

__device__ float g_P[2 * PDIM * HIDDEN];    // [s][v][j]
__device__ float g_U[NPAIR * UPITCH];       // per-pair output rows (+bias)

__device__ __forceinline__ void ffma2(unsigned long long& d,
                                      unsigned long long a,
                                      unsigned long long b) {
    asm("fma.rn.f32x2 %0, %1, %2, %0;" : "+l"(d) : "l"(a), "l"(b));
}
__device__ __forceinline__ unsigned long long dup_f32(float w) {
    unsigned long long u;
    asm("mov.b64 %0, {%1, %1};" : "=l"(u) : "f"(w));
    return u;
}
__device__ __forceinline__ float2 unpack_f32x2(unsigned long long v) {
    float2 r;
    asm("mov.b64 {%0, %1}, %2;" : "=f"(r.x), "=f"(r.y) : "l"(v));
    return r;
}

// ---------------------------------------------------------------------------
// Kernel A: P[s][v][j] = sum_k E[v][k] * W1[j][s*512+k]
// grid (16 jt, 7 vt, 2 s) = 224 blocks, 128 threads.
// E tile [16][512] staged once; W1 chunk [32][128] staged per k-chunk —
// all gmem loads coalesced. Thread = (j lane, 4 v rows), k-ascending chains.
// ---------------------------------------------------------------------------
__global__ void __launch_bounds__(128) precompute_kernel(
    const float* __restrict__ E, const float* __restrict__ W1)
{
    extern __shared__ float4 psm[];
    float4* Es4  = psm;                     // [PVT][128]
    float4* W1s4 = psm + PVT * (HIDDEN / 4); // [PJT][W1P4]

    const int jt = blockIdx.x, vt = blockIdx.y, s = blockIdx.z;
    const int tid = threadIdx.x;
    const int lane = tid & 31;   // j within tile
    const int grp  = tid >> 5;   // v group (4 rows each)
    const int vbase = vt * PVT;

    // stage E tile (coalesced, zero-fill past row 96)
    const float4* E4 = reinterpret_cast<const float4*>(E);
    const float4 z4 = make_float4(0.f, 0.f, 0.f, 0.f);
#pragma unroll
    for (int r = 0; r < PVT * (HIDDEN / 4) / 128; r++) {
        int idx = tid + 128 * r;
        int vv = idx >> 7;           // 0..15
        int c4 = idx & 127;
        int v  = vbase + vv;
        Es4[vv * 128 + c4] = (v < PDIM) ? __ldg(E4 + v * 128 + c4) : z4;
    }

    const float4* W14 = reinterpret_cast<const float4*>(W1); // row stride 256

    float acc[4];
#pragma unroll
    for (int u = 0; u < 4; u++) acc[u] = 0.f;

    for (int kb = 0; kb < HIDDEN / PKC; kb++) {
        __syncthreads();
        // stage W1 chunk [32 j][32 float4] coalesced
#pragma unroll
        for (int r = 0; r < PJT * (PKC / 4) / 128; r++) {
            int idx = tid + 128 * r;
            int row = idx >> 5;          // 0..31
            int c4  = idx & 31;
            W1s4[row * W1P4 + c4] =
                __ldg(W14 + (size_t)(jt * PJT + row) * 256 + s * 128 + kb * 32 + c4);
        }
        __syncthreads();

#pragma unroll 8
        for (int k4 = 0; k4 < PKC / 4; k4++) {
            float4 w = W1s4[lane * W1P4 + k4];
#pragma unroll
            for (int u = 0; u < 4; u++) {
                float4 e = Es4[(grp * 4 + u) * 128 + kb * 32 + k4];
                acc[u] = fmaf(e.x, w.x, acc[u]);
                acc[u] = fmaf(e.y, w.y, acc[u]);
                acc[u] = fmaf(e.z, w.z, acc[u]);
                acc[u] = fmaf(e.w, w.w, acc[u]);
            }
        }
    }

    const int j = jt * PJT + lane;
#pragma unroll
    for (int u = 0; u < 4; u++) {
        int vg = vbase + grp * 4 + u;
        if (vg < PDIM) g_P[(s * PDIM + vg) * HIDDEN + j] = acc[u];
    }
}

// ---------------------------------------------------------------------------
// Kernel B: per-pair LIF sim -> weighted spike sums S (smem), then
// U = S @ W2.T + b2*G with packed f32x2 FMAs. 148 blocks x 64 pairs, 256 thr.
// ---------------------------------------------------------------------------
__global__ void __launch_bounds__(256, 1) pair_kernel(
    const float* __restrict__ b1, const float* __restrict__ W2,
    const float* __restrict__ b2, const float* __restrict__ pbeta1,
    const float* __restrict__ pbeta2, const float* __restrict__ pthr1)
{
    extern __shared__ float sm[];
    float* Ssm = sm;                                              // [512][SPITCH]
    unsigned long long* W2s =
        reinterpret_cast<unsigned long long*>(sm + 512 * SPITCH); // [112][WP2]

    const float beta1 = fminf(fmaxf(__ldg(pbeta1), 0.1f), 0.9f);
    const float beta2 = fminf(fmaxf(__ldg(pbeta2), 0.1f), 0.9f);
    const float thr1  = fmaxf(__ldg(pthr1), 0.1f);
    const float nthr1 = -thr1;

    const int tid = threadIdx.x;

    // ---------------- phase 1: simulate 64 pairs x 512 h --------------------
    {
        const int q   = tid >> 2;   // pair slot 0..63
        const int sub = tid & 3;    // h-quarter
        int pp = blockIdx.x * 64 + q;
        if (pp >= NPAIR) pp = 0;    // junk lanes; phase-2 store is guarded
        const int a = pp / PDIM;
        const int b = pp - a * PDIM;
        const float4* p1  = reinterpret_cast<const float4*>(g_P + a * HIDDEN);
        const float4* p2  = reinterpret_cast<const float4*>(g_P + (PDIM + b) * HIDDEN);
        const float4* b14 = reinterpret_cast<const float4*>(b1);

        // prefetch o=0
        float4 n1 = __ldg(p1 + sub), n2 = __ldg(p2 + sub), nb = __ldg(b14 + sub);

#pragma unroll 1
        for (int o = 0; o < 32; o++) {
            const float4 v1 = n1, v2 = n2, vb = nb;
            if (o < 31) {
                const int h4n = sub + 4 * (o + 1);
                n1 = __ldg(p1 + h4n);
                n2 = __ldg(p2 + h4n);
                nb = __ldg(b14 + h4n);
            }
            // c = (p1 + p2) + b1  — same order as before
            float c[4], m[4], S[4], spf[4];
            c[0] = __fadd_rn(__fadd_rn(v1.x, v2.x), vb.x);
            c[1] = __fadd_rn(__fadd_rn(v1.y, v2.y), vb.y);
            c[2] = __fadd_rn(__fadd_rn(v1.z, v2.z), vb.z);
            c[3] = __fadd_rn(__fadd_rn(v1.w, v2.w), vb.w);
#pragma unroll
            for (int u = 0; u < 4; u++) { m[u] = 0.f; S[u] = 0.f; spf[u] = 0.f; }
#pragma unroll
            for (int t = 0; t < NSTEPS; t++) {
#pragma unroll
                for (int u = 0; u < 4; u++) {
                    // mm = (beta1*m + c) - spf*thr1; spf in {0,1} so the fma is
                    // bit-identical to the guarded subtract (exact product).
                    float mm = __fadd_rn(__fmul_rn(beta1, m[u]), c[u]);
                    mm = __fmaf_rn(spf[u], nthr1, mm);
                    spf[u] = (mm > thr1) ? 1.0f : 0.0f;
                    m[u] = mm;
                    S[u] = __fmaf_rn(beta2, S[u], spf[u]);
                }
            }
            const int h = (sub + 4 * o) * 4;
#pragma unroll
            for (int u = 0; u < 4; u++) Ssm[(h + u) * SPITCH + q] = S[u];
        }
    }

    // ---------------- phase 2: U = S @ W2.T (packed f32x2) ------------------
    const int tx = tid & 15;   // 4-pair group
    const int ty = tid >> 4;   // 7-p group

    unsigned long long acc01[7], acc23[7];
#pragma unroll
    for (int i = 0; i < 7; i++) { acc01[i] = 0ull; acc23[i] = 0ull; }

    for (int kb = 0; kb < HIDDEN / KC; kb++) {
        __syncthreads();   // first iter: phase-1 done; later: prev chunk consumed
        for (int idx = tid; idx < PDIM * KC; idx += 256) {
            int p = idx >> 6;
            int k = idx & 63;
            W2s[p * WP2 + k] = dup_f32(__ldg(W2 + p * HIDDEN + kb * KC + k));
        }
        __syncthreads();

#pragma unroll 4
        for (int k = 0; k < KC; k++) {
            int kg = kb * KC + k;
            ulonglong2 sv = *reinterpret_cast<const ulonglong2*>(
                Ssm + kg * SPITCH + tx * 4);
#pragma unroll
            for (int i = 0; i < 7; i++) {
                unsigned long long w2 = W2s[(ty * 7 + i) * WP2 + k];
                ffma2(acc01[i], sv.x, w2);
                ffma2(acc23[i], sv.y, w2);
            }
        }
    }

    // G = sum_{k=0..14} beta2^k via same recursion as mem2
    float G = 0.0f;
#pragma unroll
    for (int t = 0; t < NSTEPS; t++) G = __fadd_rn(__fmul_rn(beta2, G), 1.0f);

    const int ppb = blockIdx.x * 64 + tx * 4;
#pragma unroll
    for (int i = 0; i < 7; i++) {
        const int p = ty * 7 + i;
        if (p >= PDIM) break;
        const float bg = __ldg(b2 + p) * G;
        float2 f01 = unpack_f32x2(acc01[i]);
        float2 f23 = unpack_f32x2(acc23[i]);
        float av[4] = {f01.x, f01.y, f23.x, f23.y};
#pragma unroll
        for (int jj = 0; jj < 4; jj++) {
            int pp = ppb + jj;
            if (pp < NPAIR) g_U[pp * UPITCH + p] = av[jj] + bg;
        }
    }
}

// ---------------------------------------------------------------------------
// Kernel C: out[b,:] = U[pair(b),:]. One warp per output row.
// ---------------------------------------------------------------------------
__global__ void __launch_bounds__(256) scatter_kernel(
    const int* __restrict__ x, float* __restrict__ out, int B)
{
    int warp = blockIdx.x * 8 + (threadIdx.x >> 5);
    int lane = threadIdx.x & 31;
    if (warp >= B) return;
    int x0 = __ldg(x + 2 * warp);
    int x1 = __ldg(x + 2 * warp + 1);
    const float* u = g_U + (size_t)(x0 * PDIM + x1) * UPITCH;
    float* o = out + (size_t)warp * PDIM;
#pragma unroll
    for (int j = 0; j < 3; j++) o[lane + 32 * j] = u[lane + 32 * j];
    if (lane == 0) o[96] = u[96];
}

// ---------------------------------------------------------------------------
extern "C" void kernel_launch(void* const* d_in, const int* in_sizes, int n_in,
                              void* d_out, int out_size)
{
    const int*   x     = (const int*)  d_in[0];
    const float* E     = (const float*)d_in[1];
    const float* W1    = (const float*)d_in[2];
    const float* b1    = (const float*)d_in[3];
    const float* W2    = (const float*)d_in[4];
    const float* b2    = (const float*)d_in[5];
    const float* beta1 = (const float*)d_in[6];
    const float* beta2 = (const float*)d_in[7];
    const float* thr1  = (const float*)d_in[8];
    // thr2 unused in forward (lif2 reset='none'; output is mem2).

    const int B = in_sizes[0] / 2;

    const int psmemB = (PVT * (HIDDEN / 4) + PJT * W1P4) * (int)sizeof(float4); // 49664
    cudaFuncSetAttribute(precompute_kernel,
                         cudaFuncAttributeMaxDynamicSharedMemorySize, psmemB);

    const int smemB = 512 * SPITCH * (int)sizeof(float)
                    + 112 * WP2 * (int)sizeof(unsigned long long); // 197504
    cudaFuncSetAttribute(pair_kernel, cudaFuncAttributeMaxDynamicSharedMemorySize, smemB);

    precompute_kernel<<<dim3(16, 7, 2), 128, psmemB>>>(E, W1);
    pair_kernel<<<148, 256, smemB>>>(b1, W2, b2, beta1, beta2, thr1);
    scatter_kernel<<<(B + 7) / 8, 256>>>(x, (float*)d_out, B);
}

// round 5
// speedup vs baseline: 1.4107x; 1.0564x over previous
#include <cuda_runtime.h>
#include <cstdint>

// GrokkingSNN: B=32768, hidden=512, p=97, 15 steps.
//   cur1[b,j] = P1[x0,j] + P2[x1,j] + b1[j], P = E @ W1half.T  (97x512 each)
//   9409 distinct (x0,x1) pairs -> simulate per pair.
//   mem2 = (sum_t beta2^{15-t} spk_t) @ W2.T + b2 * G; scatter to 32768 rows.
// R5: packed f32x2 LIF recurrence + FSET spikes; LDS.128 k-paired W2 in GEMM;
//     one-wave register-double-buffered precompute. All bit-identical rounding.

#define HIDDEN 512
#define PDIM 97
#define NPAIR (PDIM * PDIM)   // 9409
#define NSTEPS 15
#define UPITCH 104

#define SPITCH 68   // Ssm pitch (floats)
#define WP2 66      // packed W2 pitch (8B words) — even: 16B-aligned k-pairs
#define KC 64       // K-chunk for W2 staging

// precompute tiling
#define PJT 64      // j per block
#define PVT 16      // v per block
#define W1P4 33     // W1 chunk pitch in float4 (odd -> conflict-free LDS.128)

__device__ float g_P[2 * PDIM * HIDDEN];    // [s][v][j]
__device__ float g_U[NPAIR * UPITCH];       // per-pair output rows (+bias)

typedef unsigned long long ull;

__device__ __forceinline__ void ffma2(ull& d, ull a, ull b) {
    asm("fma.rn.f32x2 %0, %1, %2, %0;" : "+l"(d) : "l"(a), "l"(b));
}
__device__ __forceinline__ ull fma2v(ull a, ull b, ull c) {
    ull d; asm("fma.rn.f32x2 %0, %1, %2, %3;" : "=l"(d) : "l"(a), "l"(b), "l"(c));
    return d;
}
__device__ __forceinline__ ull add2(ull a, ull b) {
    ull d; asm("add.rn.f32x2 %0, %1, %2;" : "=l"(d) : "l"(a), "l"(b));
    return d;
}
__device__ __forceinline__ ull mul2(ull a, ull b) {
    ull d; asm("mul.rn.f32x2 %0, %1, %2;" : "=l"(d) : "l"(a), "l"(b));
    return d;
}
__device__ __forceinline__ ull pack2(float lo, float hi) {
    ull u; asm("mov.b64 %0, {%1, %2};" : "=l"(u) : "f"(lo), "f"(hi));
    return u;
}
__device__ __forceinline__ ull dup_f32(float w) {
    ull u; asm("mov.b64 %0, {%1, %1};" : "=l"(u) : "f"(w));
    return u;
}
__device__ __forceinline__ void unpack2(ull v, float& lo, float& hi) {
    asm("mov.b64 {%0, %1}, %2;" : "=f"(lo), "=f"(hi) : "l"(v));
}
__device__ __forceinline__ float fsetgt(float a, float b) {
    float d; asm("set.gt.f32.f32 %0, %1, %2;" : "=f"(d) : "f"(a), "f"(b));
    return d;   // 1.0f if a>b else 0.0f (single FSET)
}

// ---------------------------------------------------------------------------
// Kernel A: P[s][v][j] = sum_k E[v][k] * W1[j][s*512+k]
// grid (8 jt of 64 j, 7 vt of 16 v, 2 s) = 112 blocks (one wave), 256 threads.
// E tile staged once; W1 chunks register-double-buffered. k-ascending chains.
// ---------------------------------------------------------------------------
__global__ void __launch_bounds__(256) precompute_kernel(
    const float* __restrict__ E, const float* __restrict__ W1)
{
    extern __shared__ float4 psm[];
    float4* Es4  = psm;                       // [PVT][128]
    float4* W1s4 = psm + PVT * (HIDDEN / 4);  // [PJT][W1P4]

    const int jt = blockIdx.x, vt = blockIdx.y, s = blockIdx.z;
    const int tid  = threadIdx.x;
    const int lane = tid & 63;    // j within tile
    const int grp  = tid >> 6;    // v group (4 rows each)
    const int vbase = vt * PVT;

    // stage E tile (coalesced, zero-fill past row 96)
    const float4* E4 = reinterpret_cast<const float4*>(E);
    const float4 z4 = make_float4(0.f, 0.f, 0.f, 0.f);
#pragma unroll
    for (int r = 0; r < PVT * (HIDDEN / 4) / 256; r++) {
        int idx = tid + 256 * r;
        int vv = idx >> 7;
        int c4 = idx & 127;
        int v  = vbase + vv;
        Es4[vv * 128 + c4] = (v < PDIM) ? __ldg(E4 + v * 128 + c4) : z4;
    }

    // W1 row stride = 256 float4; chunk = [64 j][32 float4]
    const float4* W14 = reinterpret_cast<const float4*>(W1);
    const int srow = tid >> 5;           // 0..7 -> rows srow, srow+8, ...
    const int sc4  = tid & 31;

    float4 r[8];
#pragma unroll
    for (int i = 0; i < 8; i++)
        r[i] = __ldg(W14 + (size_t)(jt * PJT + srow + 8 * i) * 256 + s * 128 + sc4);

    float acc[4];
#pragma unroll
    for (int u = 0; u < 4; u++) acc[u] = 0.f;

    for (int kb = 0; kb < 4; kb++) {
#pragma unroll
        for (int i = 0; i < 8; i++)
            W1s4[(srow + 8 * i) * W1P4 + sc4] = r[i];
        __syncthreads();
        if (kb < 3) {
#pragma unroll
            for (int i = 0; i < 8; i++)
                r[i] = __ldg(W14 + (size_t)(jt * PJT + srow + 8 * i) * 256
                             + s * 128 + (kb + 1) * 32 + sc4);
        }

#pragma unroll 8
        for (int k4 = 0; k4 < 32; k4++) {
            float4 w = W1s4[lane * W1P4 + k4];
#pragma unroll
            for (int u = 0; u < 4; u++) {
                float4 e = Es4[(grp * 4 + u) * 128 + kb * 32 + k4];
                acc[u] = fmaf(e.x, w.x, acc[u]);
                acc[u] = fmaf(e.y, w.y, acc[u]);
                acc[u] = fmaf(e.z, w.z, acc[u]);
                acc[u] = fmaf(e.w, w.w, acc[u]);
            }
        }
        __syncthreads();
    }

    const int j = jt * PJT + lane;
#pragma unroll
    for (int u = 0; u < 4; u++) {
        int vg = vbase + grp * 4 + u;
        if (vg < PDIM) g_P[(s * PDIM + vg) * HIDDEN + j] = acc[u];
    }
}

// ---------------------------------------------------------------------------
// Kernel B: per-pair LIF sim (packed f32x2 + FSET) -> weighted spike sums S,
// then U = S @ W2.T + b2*G (packed FFMA2, LDS.128 everywhere).
// 148 blocks x 64 pairs, 256 threads.
// ---------------------------------------------------------------------------
__global__ void __launch_bounds__(256, 1) pair_kernel(
    const float* __restrict__ b1, const float* __restrict__ W2,
    const float* __restrict__ b2, const float* __restrict__ pbeta1,
    const float* __restrict__ pbeta2, const float* __restrict__ pthr1)
{
    extern __shared__ float sm[];
    float* Ssm = sm;                                 // [512][SPITCH]
    ull* W2s = reinterpret_cast<ull*>(sm + 512 * SPITCH); // [112][WP2]

    const float beta1 = fminf(fmaxf(__ldg(pbeta1), 0.1f), 0.9f);
    const float beta2 = fminf(fmaxf(__ldg(pbeta2), 0.1f), 0.9f);
    const float thr1  = fmaxf(__ldg(pthr1), 0.1f);

    const int tid = threadIdx.x;

    // ---------------- phase 1: simulate 64 pairs x 512 h --------------------
    {
        const int q   = tid >> 2;   // pair slot 0..63
        const int sub = tid & 3;    // h-quarter
        int pp = blockIdx.x * 64 + q;
        if (pp >= NPAIR) pp = 0;    // junk lanes; phase-2 store is guarded
        const int a = pp / PDIM;
        const int b = pp - a * PDIM;
        const float4* p1  = reinterpret_cast<const float4*>(g_P + a * HIDDEN);
        const float4* p2  = reinterpret_cast<const float4*>(g_P + (PDIM + b) * HIDDEN);
        const float4* b14 = reinterpret_cast<const float4*>(b1);

        const ull bt1 = dup_f32(beta1);
        const ull bt2 = dup_f32(beta2);
        const ull nt2 = dup_f32(-thr1);

        float4 n1 = __ldg(p1 + sub), n2 = __ldg(p2 + sub), nb = __ldg(b14 + sub);

#pragma unroll 1
        for (int o = 0; o < 32; o++) {
            const float4 v1 = n1, v2 = n2, vb = nb;
            if (o < 31) {
                const int h4n = sub + 4 * (o + 1);
                n1 = __ldg(p1 + h4n);
                n2 = __ldg(p2 + h4n);
                nb = __ldg(b14 + h4n);
            }
            // c = (p1 + p2) + b1, two packed lanes each (identical rounding)
            ull c01 = add2(add2(pack2(v1.x, v1.y), pack2(v2.x, v2.y)),
                           pack2(vb.x, vb.y));
            ull c23 = add2(add2(pack2(v1.z, v1.w), pack2(v2.z, v2.w)),
                           pack2(vb.z, vb.w));

            ull m01 = 0, m23 = 0, S01 = 0, S23 = 0, sp01 = 0, sp23 = 0;
#pragma unroll
            for (int t = 0; t < NSTEPS; t++) {
                // mm = (beta1*m + c) - sp*thr1  (unfused mul+add, exact fma sub)
                m01 = fma2v(sp01, nt2, add2(mul2(bt1, m01), c01));
                m23 = fma2v(sp23, nt2, add2(mul2(bt1, m23), c23));
                float a0, a1, a2, a3;
                unpack2(m01, a0, a1);
                unpack2(m23, a2, a3);
                sp01 = pack2(fsetgt(a0, thr1), fsetgt(a1, thr1));
                sp23 = pack2(fsetgt(a2, thr1), fsetgt(a3, thr1));
                S01 = fma2v(bt2, S01, sp01);
                S23 = fma2v(bt2, S23, sp23);
            }
            float s0, s1, s2, s3;
            unpack2(S01, s0, s1);
            unpack2(S23, s2, s3);
            const int h = (sub + 4 * o) * 4;
            Ssm[(h + 0) * SPITCH + q] = s0;
            Ssm[(h + 1) * SPITCH + q] = s1;
            Ssm[(h + 2) * SPITCH + q] = s2;
            Ssm[(h + 3) * SPITCH + q] = s3;
        }
    }

    // ---------------- phase 2: U = S @ W2.T (packed, LDS.128) ---------------
    const int tx = tid & 15;   // 4-pair group
    const int ty = tid >> 4;   // 7-p group

    ull acc01[7], acc23[7];
#pragma unroll
    for (int i = 0; i < 7; i++) { acc01[i] = 0ull; acc23[i] = 0ull; }

    for (int kb = 0; kb < HIDDEN / KC; kb++) {
        __syncthreads();   // first iter: phase-1 done; later: prev chunk consumed
        for (int idx = tid; idx < PDIM * KC; idx += 256) {
            int p = idx >> 6;
            int k = idx & 63;
            W2s[p * WP2 + k] = dup_f32(__ldg(W2 + p * HIDDEN + kb * KC + k));
        }
        __syncthreads();

#pragma unroll 4
        for (int k2 = 0; k2 < KC / 2; k2++) {
            const int kg = kb * KC + 2 * k2;
            ulonglong2 svA = *reinterpret_cast<const ulonglong2*>(
                Ssm + kg * SPITCH + tx * 4);
            ulonglong2 svB = *reinterpret_cast<const ulonglong2*>(
                Ssm + (kg + 1) * SPITCH + tx * 4);
#pragma unroll
            for (int i = 0; i < 7; i++) {
                // w.x = dup W2[p][k], w.y = dup W2[p][k+1] — one LDS.128
                ulonglong2 w = *reinterpret_cast<const ulonglong2*>(
                    W2s + (ty * 7 + i) * WP2 + 2 * k2);
                ffma2(acc01[i], svA.x, w.x);   // k   (ascending order kept)
                ffma2(acc23[i], svA.y, w.x);
                ffma2(acc01[i], svB.x, w.y);   // k+1
                ffma2(acc23[i], svB.y, w.y);
            }
        }
    }

    // G = sum_{k=0..14} beta2^k via same recursion as mem2
    float G = 0.0f;
#pragma unroll
    for (int t = 0; t < NSTEPS; t++) G = __fadd_rn(__fmul_rn(beta2, G), 1.0f);

    const int ppb = blockIdx.x * 64 + tx * 4;
#pragma unroll
    for (int i = 0; i < 7; i++) {
        const int p = ty * 7 + i;
        if (p >= PDIM) break;
        const float bg = __ldg(b2 + p) * G;
        float f0, f1, f2, f3;
        unpack2(acc01[i], f0, f1);
        unpack2(acc23[i], f2, f3);
        float av[4] = {f0, f1, f2, f3};
#pragma unroll
        for (int jj = 0; jj < 4; jj++) {
            int pp = ppb + jj;
            if (pp < NPAIR) g_U[pp * UPITCH + p] = av[jj] + bg;
        }
    }
}

// ---------------------------------------------------------------------------
// Kernel C: out[b,:] = U[pair(b),:]. One warp per output row.
// ---------------------------------------------------------------------------
__global__ void __launch_bounds__(256) scatter_kernel(
    const int* __restrict__ x, float* __restrict__ out, int B)
{
    int warp = blockIdx.x * 8 + (threadIdx.x >> 5);
    int lane = threadIdx.x & 31;
    if (warp >= B) return;
    int x0 = __ldg(x + 2 * warp);
    int x1 = __ldg(x + 2 * warp + 1);
    const float* u = g_U + (size_t)(x0 * PDIM + x1) * UPITCH;
    float* o = out + (size_t)warp * PDIM;
#pragma unroll
    for (int j = 0; j < 3; j++) o[lane + 32 * j] = u[lane + 32 * j];
    if (lane == 0) o[96] = u[96];
}

// ---------------------------------------------------------------------------
extern "C" void kernel_launch(void* const* d_in, const int* in_sizes, int n_in,
                              void* d_out, int out_size)
{
    const int*   x     = (const int*)  d_in[0];
    const float* E     = (const float*)d_in[1];
    const float* W1    = (const float*)d_in[2];
    const float* b1    = (const float*)d_in[3];
    const float* W2    = (const float*)d_in[4];
    const float* b2    = (const float*)d_in[5];
    const float* beta1 = (const float*)d_in[6];
    const float* beta2 = (const float*)d_in[7];
    const float* thr1  = (const float*)d_in[8];
    // thr2 unused in forward (lif2 reset='none'; output is mem2).

    const int B = in_sizes[0] / 2;

    const int psmemB = (PVT * (HIDDEN / 4) + PJT * W1P4) * (int)sizeof(float4); // 66560
    cudaFuncSetAttribute(precompute_kernel,
                         cudaFuncAttributeMaxDynamicSharedMemorySize, psmemB);

    const int smemB = 512 * SPITCH * (int)sizeof(float)
                    + 112 * WP2 * (int)sizeof(ull); // 198400
    cudaFuncSetAttribute(pair_kernel, cudaFuncAttributeMaxDynamicSharedMemorySize, smemB);

    precompute_kernel<<<dim3(8, 7, 2), 256, psmemB>>>(E, W1);
    pair_kernel<<<148, 256, smemB>>>(b1, W2, b2, beta1, beta2, thr1);
    scatter_kernel<<<(B + 7) / 8, 256>>>(x, (float*)d_out, B);
}